// round 16
// baseline (speedup 1.0000x reference)
#include <cuda_runtime.h>
#include <cstdint>

#define BB 4
#define SS 512
#define DD 128
#define HH 8
#define SCP 516     // scores pitch (multiple of 4 -> aligned float4 PV loads)

// scratch (static device memory; no runtime allocation)
__device__ float g_q[BB*SS*DD];
__device__ float g_k[BB*SS*DD];
__device__ float g_v[BB*SS*DD];

// ---------------- f32x2 helpers ----------------
__device__ __forceinline__ unsigned long long pack2(float x) {
    unsigned long long r;
    asm("mov.b64 %0, {%1, %1};" : "=l"(r) : "f"(x));
    return r;
}
__device__ __forceinline__ unsigned long long pack2v(float lo, float hi) {
    unsigned long long r;
    asm("mov.b64 %0, {%1, %2};" : "=l"(r) : "f"(lo), "f"(hi));
    return r;
}
__device__ __forceinline__ void fma2(unsigned long long& d, unsigned long long a, unsigned long long b) {
    asm("fma.rn.f32x2 %0, %1, %2, %0;" : "+l"(d) : "l"(a), "l"(b));
}
__device__ __forceinline__ void unpack2(unsigned long long v, float& lo, float& hi) {
    asm("mov.b64 {%0, %1}, %2;" : "=f"(lo), "=f"(hi) : "l"(v));
}
__device__ __forceinline__ unsigned int smem_u32(const void* p) {
    return (unsigned int)__cvta_generic_to_shared(p);
}

// ---------------------------------------------------------------------------
// Kernel A: QKV projection with smem-staged weights. grid=(128,3), block=256
// ---------------------------------------------------------------------------
__global__ __launch_bounds__(256) void qkv_kernel(
    const float* __restrict__ x,
    const float* __restrict__ wq, const float* __restrict__ bq,
    const float* __restrict__ wk, const float* __restrict__ bk,
    const float* __restrict__ wv, const float* __restrict__ bv)
{
    extern __shared__ float sm[];
    float* ws = sm;                 // [128][128]
    float (*xs)[128] = (float(*)[128])(sm + 128 * 128);   // [16][128]

    const int t = threadIdx.x;
    const int mat = blockIdx.y;
    const int row0 = blockIdx.x * 16;

    const float* W    = (mat == 0) ? wq : (mat == 1) ? wk : wv;
    const float* bias = (mat == 0) ? bq : (mat == 1) ? bk : bv;
    float* out        = (mat == 0) ? g_q : (mat == 1) ? g_k : g_v;

    #pragma unroll
    for (int i = t; i < 4096; i += 256)
        ((float4*)ws)[i] = ((const float4*)W)[i];
    #pragma unroll
    for (int i = t; i < 512; i += 256)
        ((float4*)xs)[i] = ((const float4*)(x + (size_t)row0 * DD))[i];
    __syncthreads();

    const int c4 = t & 31;
    const int rg = t >> 5;
    const ulonglong2* W2 = (const ulonglong2*)ws;

    unsigned long long acc[2][2];
    acc[0][0] = acc[0][1] = acc[1][0] = acc[1][1] = 0ull;

    #pragma unroll 8
    for (int d = 0; d < 128; d++) {
        ulonglong2 w = W2[d * 32 + c4];
        #pragma unroll
        for (int r = 0; r < 2; r++) {
            unsigned long long xr = pack2(xs[rg * 2 + r][d]);
            fma2(acc[r][0], xr, w.x);
            fma2(acc[r][1], xr, w.y);
        }
    }
    float4 bb = ((const float4*)bias)[c4];
    #pragma unroll
    for (int r = 0; r < 2; r++) {
        float4 o;
        unpack2(acc[r][0], o.x, o.y);
        unpack2(acc[r][1], o.z, o.w);
        o.x += bb.x; o.y += bb.y; o.z += bb.z; o.w += bb.w;
        ((float4*)(out + (size_t)(row0 + rg * 2 + r) * DD))[c4] = o;
    }
}

// ---------------------------------------------------------------------------
// Kernel B: MEGA — fused st_bias stream + attention + out-proj + LayerNorm.
// grid = 512 (b = bx>>7, q0 = (bx&127)*4), block = 256 (8 warps), 2 CTAs/SM.
// Phase 0: bias -> scores. Warp w = (q=w>>1, khalf=w&1) owns 256 st rows.
//   4 tasks x 64 rows; 8 slabs of 16 d each (pitch 20, single-buffer cp.async);
//   lane owns rows {l, l+32}; weights = smem u64 broadcasts; zero shuffles.
// Phase 1: scores += qk/4 (8 chunks of 64 K rows; thread = (q, kl)).
// Phase 2: softmax (+mask). Phase 3: PV (warp = head, probs via LDS.128).
// Epilogue: wo -> scores region; y = att@wo+bo+x; LN; write d_out.
// smem = 115328 B (<= 116224 for 2 CTAs/SM).
// ---------------------------------------------------------------------------
__global__ __launch_bounds__(256, 2) void mega_kernel(
    const float* __restrict__ st, const float* __restrict__ wst,
    const int* __restrict__ mask, const float* __restrict__ x,
    const float* __restrict__ wo, const float* __restrict__ bo,
    const float* __restrict__ lng, const float* __restrict__ lnb,
    float* __restrict__ out)
{
    extern __shared__ float smem[];
    float* scores = smem;                         // [32][SCP] = 16512 fl; later wo[128][128]
    float* stage  = smem + 32 * SCP;              // 10240 fl: bias slabs / K chunks / epilogue
    float* qs     = stage + 10240;                // [4][128] = 512
    float* mask_s = qs + 512;                     // [512]
    float* rinv_s = mask_s + 512;                 // [32]
    unsigned long long* wp = (unsigned long long*)(rinv_s + 32);  // [64 dp][8 h] = 1024 fl

    const int tid  = threadIdx.x;
    const int lane = tid & 31;
    const int wid  = tid >> 5;
    const int b    = blockIdx.x >> 7;
    const int q0   = (blockIdx.x & 127) * 4;

    // ---- init: weight table, q tile, mask ----
    #pragma unroll
    for (int idx = tid; idx < 512; idx += 256) {
        int j = idx >> 3, h = idx & 7;
        wp[idx] = pack2v(wst[(2 * j) * HH + h], wst[(2 * j + 1) * HH + h]);
    }
    if (tid < 128) {
        int r = tid >> 5, c4 = tid & 31;
        ((float4*)(qs + r * 128))[c4] =
            ((const float4*)(g_q + (size_t)(b * SS + q0 + r) * DD))[c4];
    }
    #pragma unroll
    for (int i = tid; i < 512; i += 256)
        mask_s[i] = mask[b * SS + i] ? -10000.0f : 0.0f;
    __syncthreads();

    // ---------------- Phase 0: bias -> scores (stream 1MB of st) -------------
    {
        const int q  = wid >> 1;
        const int kh = wid & 1;
        float* stg = stage + wid * 1280;          // 64 rows x pitch 20
        const unsigned stgu = smem_u32(stg);
        const int prow = lane >> 2;               // 0..7
        const int pchk = lane & 3;                // 16B chunk
        const size_t R = ((size_t)(b * SS + q0 + q)) * SS + kh * 256;

        for (int t4 = 0; t4 < 4; t4++) {
            unsigned long long accA[8], accB[8];
            #pragma unroll
            for (int h = 0; h < 8; h++) { accA[h] = 0ull; accB[h] = 0ull; }

            for (int s = 0; s < 8; s++) {
                // stage slab: 64 rows x 64B (d window s), single buffer
                {
                    const char* gsrc = (const char*)st
                        + (R + t4 * 64 + prow) * 512 + s * 64 + pchk * 16;
                    unsigned sdst = stgu + prow * 80 + pchk * 16;
                    #pragma unroll
                    for (int ii = 0; ii < 8; ii++)
                        asm volatile("cp.async.cg.shared.global [%0], [%1], 16;"
                                     :: "r"(sdst + ii * 8 * 80),
                                        "l"(gsrc + (size_t)ii * 8 * 512)
                                     : "memory");
                    asm volatile("cp.async.commit_group;");
                    asm volatile("cp.async.wait_group 0;" ::: "memory");
                    __syncwarp();
                }
                const unsigned long long* wsl = wp + s * 64;   // 8 dp x 8 h
                const ulonglong2* eAp = (const ulonglong2*)(stg + lane * 20);
                const ulonglong2* eBp = (const ulonglong2*)(stg + (lane + 32) * 20);
                ulonglong2 eA0 = eAp[0], eA1 = eAp[1];
                ulonglong2 eB0 = eBp[0], eB1 = eBp[1];
                #pragma unroll
                for (int h = 0; h < 8; h++) {
                    unsigned long long w0 = wsl[0 * 8 + h];
                    unsigned long long w1 = wsl[1 * 8 + h];
                    unsigned long long w2 = wsl[2 * 8 + h];
                    unsigned long long w3 = wsl[3 * 8 + h];
                    fma2(accA[h], eA0.x, w0); fma2(accB[h], eB0.x, w0);
                    fma2(accA[h], eA0.y, w1); fma2(accB[h], eB0.y, w1);
                    fma2(accA[h], eA1.x, w2); fma2(accB[h], eB1.x, w2);
                    fma2(accA[h], eA1.y, w3); fma2(accB[h], eB1.y, w3);
                }
                #pragma unroll
                for (int h = 0; h < 8; h++) {
                    unsigned long long w4 = wsl[4 * 8 + h];
                    unsigned long long w5 = wsl[5 * 8 + h];
                    unsigned long long w6 = wsl[6 * 8 + h];
                    unsigned long long w7 = wsl[7 * 8 + h];
                    ulonglong2 fA0 = eAp[2], fA1 = eAp[3];
                    ulonglong2 fB0 = eBp[2], fB1 = eBp[3];
                    fma2(accA[h], fA0.x, w4); fma2(accB[h], fB0.x, w4);
                    fma2(accA[h], fA0.y, w5); fma2(accB[h], fB0.y, w5);
                    fma2(accA[h], fA1.x, w6); fma2(accB[h], fB1.x, w6);
                    fma2(accA[h], fA1.y, w7); fma2(accB[h], fB1.y, w7);
                }
                __syncwarp();   // all lanes done reading buffer before next cp
            }
            // write 2 rows x 8 heads to scores
            const int kA = kh * 256 + t4 * 64 + lane;
            const int kB = kA + 32;
            #pragma unroll
            for (int h = 0; h < 8; h++) {
                float lo, hi;
                unpack2(accA[h], lo, hi);
                scores[(q * 8 + h) * SCP + kA] = lo + hi;
                unpack2(accB[h], lo, hi);
                scores[(q * 8 + h) * SCP + kB] = lo + hi;
            }
        }
    }
    __syncthreads();

    // ---------------- Phase 1: scores += qk/4 (8 chunks of 64 K rows) --------
    {
        const int q  = tid >> 6;          // 0..3 (uniform per warp)
        const int kl = tid & 63;
        const ulonglong2* qr = (const ulonglong2*)(qs + q * 128);

        for (int c = 0; c < 8; c++) {
            const float4* kg = (const float4*)(g_k + (size_t)(b * SS + c * 64) * DD);
            #pragma unroll
            for (int idx = tid; idx < 2048; idx += 256)
                ((float4*)stage)[(idx >> 5) * 33 + (idx & 31)] = kg[idx];
            __syncthreads();

            unsigned long long acc2[8];
            #pragma unroll
            for (int h = 0; h < 8; h++) acc2[h] = 0ull;
            const ulonglong2* kr = (const ulonglong2*)(stage + kl * 132);
            #pragma unroll
            for (int j = 0; j < 32; j++) {
                ulonglong2 kk2 = kr[j];     // conflict-free (stride 132)
                ulonglong2 a   = qr[j];     // warp-broadcast
                fma2(acc2[j >> 2], a.x, kk2.x);
                fma2(acc2[j >> 2], a.y, kk2.y);
            }
            const int kidx = c * 64 + kl;
            float* sd = scores + (q * 8) * SCP + kidx;
            #pragma unroll
            for (int h = 0; h < 8; h++) {
                float lo, hi;
                unpack2(acc2[h], lo, hi);
                sd[h * SCP] = fmaf(lo + hi, 0.25f, sd[h * SCP]);
            }
            __syncthreads();
        }
    }

    // ---------------- Phase 2: softmax per (q,h) row ----------------
    for (int rr = wid; rr < 32; rr += 8) {
        float* srow = scores + rr * SCP;
        float vals[16];
        float mx = -1e30f;
        #pragma unroll
        for (int j = 0; j < 16; j++) {
            int k = lane + 32 * j;
            float v = srow[k] + mask_s[k];
            vals[j] = v;
            mx = fmaxf(mx, v);
        }
        #pragma unroll
        for (int o = 16; o > 0; o >>= 1) mx = fmaxf(mx, __shfl_xor_sync(0xffffffffu, mx, o));
        float sum = 0.f;
        #pragma unroll
        for (int j = 0; j < 16; j++) {
            float e = __expf(vals[j] - mx);
            srow[lane + 32 * j] = e;
            sum += e;
        }
        #pragma unroll
        for (int o = 16; o > 0; o >>= 1) sum += __shfl_xor_sync(0xffffffffu, sum, o);
        if (lane == 0) rinv_s[rr] = 1.0f / sum;
    }
    __syncthreads();

    // ---------------- Phase 3: PV (warp = head; probs via LDS.128) -----------
    float* outp  = stage;          // [8h][4q][16e] = 512 fl
    float* att_s = stage + 512;    // [4][132]
    float* ys    = stage + 1040;   // [4][132]
    {
        const int h  = wid;
        const int e  = lane & 15;
        const int kk = lane >> 4;     // 0/1
        const float* vbase = g_v + (size_t)(b * SS) * DD + h * 16 + e;

        unsigned long long acc2[4];
        #pragma unroll
        for (int q = 0; q < 4; q++) acc2[q] = 0ull;

        #pragma unroll 4
        for (int i = 0; i < 64; i++) {
            const int k4 = kk * 4 + i * 8;
            float v0 = vbase[(size_t)(k4 + 0) * DD];
            float v1 = vbase[(size_t)(k4 + 1) * DD];
            float v2 = vbase[(size_t)(k4 + 2) * DD];
            float v3 = vbase[(size_t)(k4 + 3) * DD];
            unsigned long long vp01 = pack2v(v0, v1);
            unsigned long long vp23 = pack2v(v2, v3);
            #pragma unroll
            for (int q = 0; q < 4; q++) {
                ulonglong2 p2 = *(const ulonglong2*)(scores + (q * 8 + h) * SCP + k4);
                fma2(acc2[q], p2.x, vp01);
                fma2(acc2[q], p2.y, vp23);
            }
        }
        __syncthreads();   // all warps done reading stage (chunk 7) & scores probs? probs still needed below: outp (stage) write is safe; scores untouched
        #pragma unroll
        for (int q = 0; q < 4; q++) {
            float lo, hi;
            unpack2(acc2[q], lo, hi);
            float s = lo + hi;
            s += __shfl_xor_sync(0xffffffffu, s, 16);
            if (lane < 16)
                outp[(h * 4 + q) * 16 + e] = s;
        }
    }
    __syncthreads();

    // ---------------- Epilogue A: normalize att; stage wo into scores --------
    #pragma unroll
    for (int id = tid; id < 512; id += 256) {
        int e = id & 15, h = (id >> 4) & 7, q = id >> 7;
        att_s[q * 132 + h * 16 + e] = outp[(h * 4 + q) * 16 + e] * rinv_s[q * 8 + h];
    }
    __syncthreads();   // att_s complete; PV prob reads done -> scores reusable
    #pragma unroll
    for (int i = tid; i < 4096; i += 256)
        ((float4*)scores)[i] = ((const float4*)wo)[i];
    __syncthreads();

    // ---------------- Epilogue B: y = att @ wo + bo + x ----------------------
    {
        const int row = tid >> 6;      // 0..3
        const int cp  = tid & 63;      // column pair
        const float* arow = att_s + row * 132;
        const unsigned long long* wsl = (const unsigned long long*)scores + cp;

        unsigned long long acc = 0ull;
        #pragma unroll 8
        for (int d = 0; d < 128; d++)
            fma2(acc, pack2(arow[d]), wsl[d * 64]);

        float lo, hi;
        unpack2(acc, lo, hi);
        float2 bo2 = *(const float2*)(bo + cp * 2);
        float2 x2  = *(const float2*)(x + (size_t)(b * SS + q0 + row) * DD + cp * 2);
        ys[row * 132 + cp * 2]     = lo + bo2.x + x2.x;
        ys[row * 132 + cp * 2 + 1] = hi + bo2.y + x2.y;
    }
    __syncthreads();

    // ---------------- Epilogue C: LayerNorm (warps 0-3, 1 row each) ----------
    if (wid < 4) {
        float4 v = ((float4*)(ys + wid * 132))[lane];
        float s = v.x + v.y + v.z + v.w;
        #pragma unroll
        for (int o = 16; o > 0; o >>= 1) s += __shfl_xor_sync(0xffffffffu, s, o);
        float mu = s * (1.f / 128.f);
        float dx = v.x - mu, dy = v.y - mu, dz = v.z - mu, dw = v.w - mu;
        float ss = dx * dx + dy * dy + dz * dz + dw * dw;
        #pragma unroll
        for (int o = 16; o > 0; o >>= 1) ss += __shfl_xor_sync(0xffffffffu, ss, o);
        float rstd = rsqrtf(ss * (1.f / 128.f) + 1e-5f);
        float4 gg  = ((const float4*)lng)[lane];
        float4 bb2 = ((const float4*)lnb)[lane];
        float4 o4;
        o4.x = dx * rstd * gg.x + bb2.x;
        o4.y = dy * rstd * gg.y + bb2.y;
        o4.z = dz * rstd * gg.z + bb2.z;
        o4.w = dw * rstd * gg.w + bb2.w;
        ((float4*)(out + (size_t)(b * SS + q0 + wid) * DD))[lane] = o4;
    }
}

// ---------------------------------------------------------------------------
extern "C" void kernel_launch(void* const* d_in, const int* in_sizes, int n_in,
                              void* d_out, int out_size)
{
    const float* x    = (const float*)d_in[0];
    const float* st   = (const float*)d_in[1];
    const int*   mask = (const int*)  d_in[2];
    const float* wq   = (const float*)d_in[3];
    const float* bq   = (const float*)d_in[4];
    const float* wk   = (const float*)d_in[5];
    const float* bk   = (const float*)d_in[6];
    const float* wv   = (const float*)d_in[7];
    const float* bv   = (const float*)d_in[8];
    const float* wo   = (const float*)d_in[9];
    const float* bo   = (const float*)d_in[10];
    const float* wst  = (const float*)d_in[11];
    const float* lng  = (const float*)d_in[12];
    const float* lnb  = (const float*)d_in[13];
    float* out = (float*)d_out;

    const int SMEM_QKV  = (128 * 128 + 16 * 128) * 4;                          // 73728 B
    const int SMEM_MEGA = (32 * SCP + 10240 + 512 + 512 + 32 + 1024) * 4;      // 115328 B
    cudaFuncSetAttribute(qkv_kernel,  cudaFuncAttributeMaxDynamicSharedMemorySize, SMEM_QKV);
    cudaFuncSetAttribute(mega_kernel, cudaFuncAttributeMaxDynamicSharedMemorySize, SMEM_MEGA);

    qkv_kernel<<<dim3(128, 3), 256, SMEM_QKV>>>(x, wq, bq, wk, bk, wv, bv);
    mega_kernel<<<512, 256, SMEM_MEGA>>>(st, wst, mask, x, wo, bo, lng, lnb, out);
}

// round 17
// speedup vs baseline: 1.0121x; 1.0121x over previous
#include <cuda_runtime.h>
#include <cstdint>

#define BB 4
#define SS 512
#define DD 128
#define HH 8
#define SCP 516     // scores pitch (multiple of 4 -> aligned float4 PV loads)

// scratch (static device memory; no runtime allocation)
__device__ float g_q[BB*SS*DD];
__device__ float g_k[BB*SS*DD];
__device__ float g_v[BB*SS*DD];

// ---------------- f32x2 helpers ----------------
__device__ __forceinline__ unsigned long long pack2(float x) {
    unsigned long long r;
    asm("mov.b64 %0, {%1, %1};" : "=l"(r) : "f"(x));
    return r;
}
__device__ __forceinline__ unsigned long long pack2v(float lo, float hi) {
    unsigned long long r;
    asm("mov.b64 %0, {%1, %2};" : "=l"(r) : "f"(lo), "f"(hi));
    return r;
}
__device__ __forceinline__ void fma2(unsigned long long& d, unsigned long long a, unsigned long long b) {
    asm("fma.rn.f32x2 %0, %1, %2, %0;" : "+l"(d) : "l"(a), "l"(b));
}
__device__ __forceinline__ void unpack2(unsigned long long v, float& lo, float& hi) {
    asm("mov.b64 {%0, %1}, %2;" : "=f"(lo), "=f"(hi) : "l"(v));
}
__device__ __forceinline__ unsigned int smem_u32(const void* p) {
    return (unsigned int)__cvta_generic_to_shared(p);
}

// ---------------------------------------------------------------------------
// Kernel A: QKV projection with smem-staged weights. grid=(128,3), block=256
// ---------------------------------------------------------------------------
__global__ __launch_bounds__(256) void qkv_kernel(
    const float* __restrict__ x,
    const float* __restrict__ wq, const float* __restrict__ bq,
    const float* __restrict__ wk, const float* __restrict__ bk,
    const float* __restrict__ wv, const float* __restrict__ bv)
{
    extern __shared__ float sm[];
    float* ws = sm;                 // [128][128]
    float (*xs)[128] = (float(*)[128])(sm + 128 * 128);   // [16][128]

    const int t = threadIdx.x;
    const int mat = blockIdx.y;
    const int row0 = blockIdx.x * 16;

    const float* W    = (mat == 0) ? wq : (mat == 1) ? wk : wv;
    const float* bias = (mat == 0) ? bq : (mat == 1) ? bk : bv;
    float* out        = (mat == 0) ? g_q : (mat == 1) ? g_k : g_v;

    #pragma unroll
    for (int i = t; i < 4096; i += 256)
        ((float4*)ws)[i] = ((const float4*)W)[i];
    #pragma unroll
    for (int i = t; i < 512; i += 256)
        ((float4*)xs)[i] = ((const float4*)(x + (size_t)row0 * DD))[i];
    __syncthreads();

    const int c4 = t & 31;
    const int rg = t >> 5;
    const ulonglong2* W2 = (const ulonglong2*)ws;

    unsigned long long acc[2][2];
    acc[0][0] = acc[0][1] = acc[1][0] = acc[1][1] = 0ull;

    #pragma unroll 8
    for (int d = 0; d < 128; d++) {
        ulonglong2 w = W2[d * 32 + c4];
        #pragma unroll
        for (int r = 0; r < 2; r++) {
            unsigned long long xr = pack2(xs[rg * 2 + r][d]);
            fma2(acc[r][0], xr, w.x);
            fma2(acc[r][1], xr, w.y);
        }
    }
    float4 bb = ((const float4*)bias)[c4];
    #pragma unroll
    for (int r = 0; r < 2; r++) {
        float4 o;
        unpack2(acc[r][0], o.x, o.y);
        unpack2(acc[r][1], o.z, o.w);
        o.x += bb.x; o.y += bb.y; o.z += bb.z; o.w += bb.w;
        ((float4*)(out + (size_t)(row0 + rg * 2 + r) * DD))[c4] = o;
    }
}

// ---------------------------------------------------------------------------
// Kernel B: MEGA — fused st_bias stream + attention + out-proj + LayerNorm.
// grid = 512 (b = bx>>7, q0 = (bx&127)*4), block = 256 (8 warps), 2 CTAs/SM.
// STAGGERED: co-resident CTAs (b, b+148) run {phase0, phase1} in opposite
// order so one streams st_emb while the other computes qk.
// smem = 115328 B (2 CTAs/SM).
// ---------------------------------------------------------------------------
__global__ __launch_bounds__(256, 2) void mega_kernel(
    const float* __restrict__ st, const float* __restrict__ wst,
    const int* __restrict__ mask, const float* __restrict__ x,
    const float* __restrict__ wo, const float* __restrict__ bo,
    const float* __restrict__ lng, const float* __restrict__ lnb,
    float* __restrict__ out)
{
    extern __shared__ float smem[];
    float* scores = smem;                         // [32][SCP]; later wo[128][128]
    float* stage  = smem + 32 * SCP;              // 10240 fl: slabs / K chunks / epilogue
    float* qs     = stage + 10240;                // [4][128]
    float* mask_s = qs + 512;                     // [512]
    float* rinv_s = mask_s + 512;                 // [32]
    unsigned long long* wp = (unsigned long long*)(rinv_s + 32);  // [8 h][64 dp]

    const int tid  = threadIdx.x;
    const int lane = tid & 31;
    const int wid  = tid >> 5;
    const int b    = blockIdx.x >> 7;
    const int q0   = (blockIdx.x & 127) * 4;

    // ---- init: weight table [h][dp], q tile, mask ----
    #pragma unroll
    for (int idx = tid; idx < 512; idx += 256) {
        int h = idx >> 6, j = idx & 63;
        wp[idx] = pack2v(wst[(2 * j) * HH + h], wst[(2 * j + 1) * HH + h]);
    }
    if (tid < 128) {
        int r = tid >> 5, c4 = tid & 31;
        ((float4*)(qs + r * 128))[c4] =
            ((const float4*)(g_q + (size_t)(b * SS + q0 + r) * DD))[c4];
    }
    #pragma unroll
    for (int i = tid; i < 512; i += 256)
        mask_s[i] = mask[b * SS + i] ? -10000.0f : 0.0f;
    __syncthreads();

    // ---------------- Phase 0: bias stream (write or add into scores) --------
    auto phase0 = [&](const bool add_mode) {
        const int q  = wid >> 1;
        const int kh = wid & 1;
        float* stg = stage + wid * 1280;          // 64 rows x pitch 20
        const unsigned stgu = smem_u32(stg);
        const int prow = lane >> 2;
        const int pchk = lane & 3;
        const size_t R = ((size_t)(b * SS + q0 + q)) * SS + kh * 256;

        for (int t4 = 0; t4 < 4; t4++) {
            unsigned long long accA[8], accB[8];
            #pragma unroll
            for (int h = 0; h < 8; h++) { accA[h] = 0ull; accB[h] = 0ull; }

            for (int s = 0; s < 8; s++) {
                {
                    const char* gsrc = (const char*)st
                        + (R + t4 * 64 + prow) * 512 + s * 64 + pchk * 16;
                    unsigned sdst = stgu + prow * 80 + pchk * 16;
                    #pragma unroll
                    for (int ii = 0; ii < 8; ii++)
                        asm volatile("cp.async.cg.shared.global [%0], [%1], 16;"
                                     :: "r"(sdst + ii * 8 * 80),
                                        "l"(gsrc + (size_t)ii * 8 * 512)
                                     : "memory");
                    asm volatile("cp.async.commit_group;");
                    asm volatile("cp.async.wait_group 0;" ::: "memory");
                    __syncwarp();
                }
                const ulonglong2* eAp = (const ulonglong2*)(stg + lane * 20);
                const ulonglong2* eBp = (const ulonglong2*)(stg + (lane + 32) * 20);
                ulonglong2 eA0 = eAp[0], eA1 = eAp[1], eA2 = eAp[2], eA3 = eAp[3];
                ulonglong2 eB0 = eBp[0], eB1 = eBp[1], eB2 = eBp[2], eB3 = eBp[3];
                #pragma unroll
                for (int h = 0; h < 8; h++) {
                    const ulonglong2* wh = (const ulonglong2*)(wp + h * 64 + s * 8);
                    ulonglong2 w01 = wh[0], w23 = wh[1], w45 = wh[2], w67 = wh[3];
                    fma2(accA[h], eA0.x, w01.x); fma2(accB[h], eB0.x, w01.x);
                    fma2(accA[h], eA0.y, w01.y); fma2(accB[h], eB0.y, w01.y);
                    fma2(accA[h], eA1.x, w23.x); fma2(accB[h], eB1.x, w23.x);
                    fma2(accA[h], eA1.y, w23.y); fma2(accB[h], eB1.y, w23.y);
                    fma2(accA[h], eA2.x, w45.x); fma2(accB[h], eB2.x, w45.x);
                    fma2(accA[h], eA2.y, w45.y); fma2(accB[h], eB2.y, w45.y);
                    fma2(accA[h], eA3.x, w67.x); fma2(accB[h], eB3.x, w67.x);
                    fma2(accA[h], eA3.y, w67.y); fma2(accB[h], eB3.y, w67.y);
                }
                __syncwarp();
            }
            const int kA = kh * 256 + t4 * 64 + lane;
            const int kB = kA + 32;
            #pragma unroll
            for (int h = 0; h < 8; h++) {
                float loA, hiA, loB, hiB;
                unpack2(accA[h], loA, hiA);
                unpack2(accB[h], loB, hiB);
                float vA = loA + hiA, vB = loB + hiB;
                float* pA = scores + (q * 8 + h) * SCP + kA;
                float* pB = scores + (q * 8 + h) * SCP + kB;
                if (add_mode) { *pA += vA; *pB += vB; }
                else          { *pA  = vA; *pB  = vB; }
            }
        }
    };

    // ---------------- Phase 1: qk/4 (write or add into scores) ---------------
    auto phase1 = [&](const bool add_mode) {
        const int q  = tid >> 6;          // 0..3 (uniform per warp)
        const int kl = tid & 63;
        const ulonglong2* qr = (const ulonglong2*)(qs + q * 128);

        for (int c = 0; c < 8; c++) {
            const float4* kg = (const float4*)(g_k + (size_t)(b * SS + c * 64) * DD);
            #pragma unroll
            for (int idx = tid; idx < 2048; idx += 256)
                ((float4*)stage)[(idx >> 5) * 33 + (idx & 31)] = kg[idx];
            __syncthreads();

            unsigned long long acc2[8];
            #pragma unroll
            for (int h = 0; h < 8; h++) acc2[h] = 0ull;
            const ulonglong2* kr = (const ulonglong2*)(stage + kl * 132);
            #pragma unroll
            for (int j = 0; j < 32; j++) {
                ulonglong2 kk2 = kr[j];     // conflict-free (stride 132)
                ulonglong2 a   = qr[j];     // warp-broadcast
                fma2(acc2[j >> 2], a.x, kk2.x);
                fma2(acc2[j >> 2], a.y, kk2.y);
            }
            const int kidx = c * 64 + kl;
            float* sd = scores + (q * 8) * SCP + kidx;
            #pragma unroll
            for (int h = 0; h < 8; h++) {
                float lo, hi;
                unpack2(acc2[h], lo, hi);
                float v = (lo + hi) * 0.25f;
                if (add_mode) sd[h * SCP] += v;
                else          sd[h * SCP]  = v;
            }
            __syncthreads();
        }
    };

    // STAGGER: co-resident CTAs (bid, bid+148) take opposite orders.
    const bool bias_first = (((blockIdx.x / 148) & 1) == 0);
    if (bias_first) {
        phase0(false);
        __syncthreads();
        phase1(true);
    } else {
        phase1(false);
        __syncthreads();
        phase0(true);
    }
    __syncthreads();

    // ---------------- Phase 2: softmax per (q,h) row ----------------
    for (int rr = wid; rr < 32; rr += 8) {
        float* srow = scores + rr * SCP;
        float vals[16];
        float mx = -1e30f;
        #pragma unroll
        for (int j = 0; j < 16; j++) {
            int k = lane + 32 * j;
            float v = srow[k] + mask_s[k];
            vals[j] = v;
            mx = fmaxf(mx, v);
        }
        #pragma unroll
        for (int o = 16; o > 0; o >>= 1) mx = fmaxf(mx, __shfl_xor_sync(0xffffffffu, mx, o));
        float sum = 0.f;
        #pragma unroll
        for (int j = 0; j < 16; j++) {
            float e = __expf(vals[j] - mx);
            srow[lane + 32 * j] = e;
            sum += e;
        }
        #pragma unroll
        for (int o = 16; o > 0; o >>= 1) sum += __shfl_xor_sync(0xffffffffu, sum, o);
        if (lane == 0) rinv_s[rr] = 1.0f / sum;
    }
    __syncthreads();

    // ---------------- Phase 3: PV (warp = head; probs via LDS.128) -----------
    float* outp  = stage;          // [8h][4q][16e] = 512 fl
    float* att_s = stage + 512;    // [4][132]
    float* ys    = stage + 1040;   // [4][132]
    {
        const int h  = wid;
        const int e  = lane & 15;
        const int kk = lane >> 4;     // 0/1
        const float* vbase = g_v + (size_t)(b * SS) * DD + h * 16 + e;

        unsigned long long acc2[4];
        #pragma unroll
        for (int q = 0; q < 4; q++) acc2[q] = 0ull;

        #pragma unroll 4
        for (int i = 0; i < 64; i++) {
            const int k4 = kk * 4 + i * 8;
            float v0 = vbase[(size_t)(k4 + 0) * DD];
            float v1 = vbase[(size_t)(k4 + 1) * DD];
            float v2 = vbase[(size_t)(k4 + 2) * DD];
            float v3 = vbase[(size_t)(k4 + 3) * DD];
            unsigned long long vp01 = pack2v(v0, v1);
            unsigned long long vp23 = pack2v(v2, v3);
            #pragma unroll
            for (int q = 0; q < 4; q++) {
                ulonglong2 p2 = *(const ulonglong2*)(scores + (q * 8 + h) * SCP + k4);
                fma2(acc2[q], p2.x, vp01);
                fma2(acc2[q], p2.y, vp23);
            }
        }
        __syncthreads();   // stage (K chunks) no longer needed; outp writes safe
        #pragma unroll
        for (int q = 0; q < 4; q++) {
            float lo, hi;
            unpack2(acc2[q], lo, hi);
            float s = lo + hi;
            s += __shfl_xor_sync(0xffffffffu, s, 16);
            if (lane < 16)
                outp[(h * 4 + q) * 16 + e] = s;
        }
    }
    __syncthreads();

    // ---------------- Epilogue A: normalize att; stage wo into scores --------
    #pragma unroll
    for (int id = tid; id < 512; id += 256) {
        int e = id & 15, h = (id >> 4) & 7, q = id >> 7;
        att_s[q * 132 + h * 16 + e] = outp[(h * 4 + q) * 16 + e] * rinv_s[q * 8 + h];
    }
    __syncthreads();   // att_s complete; scores (probs) reads done -> reusable
    #pragma unroll
    for (int i = tid; i < 4096; i += 256)
        ((float4*)scores)[i] = ((const float4*)wo)[i];
    __syncthreads();

    // ---------------- Epilogue B: y = att @ wo + bo + x ----------------------
    {
        const int row = tid >> 6;      // 0..3
        const int cp  = tid & 63;      // column pair
        const float* arow = att_s + row * 132;
        const unsigned long long* wsl = (const unsigned long long*)scores + cp;

        unsigned long long acc = 0ull;
        #pragma unroll 8
        for (int d = 0; d < 128; d++)
            fma2(acc, pack2(arow[d]), wsl[d * 64]);

        float lo, hi;
        unpack2(acc, lo, hi);
        float2 bo2 = *(const float2*)(bo + cp * 2);
        float2 x2  = *(const float2*)(x + (size_t)(b * SS + q0 + row) * DD + cp * 2);
        ys[row * 132 + cp * 2]     = lo + bo2.x + x2.x;
        ys[row * 132 + cp * 2 + 1] = hi + bo2.y + x2.y;
    }
    __syncthreads();

    // ---------------- Epilogue C: LayerNorm (warps 0-3, 1 row each) ----------
    if (wid < 4) {
        float4 v = ((float4*)(ys + wid * 132))[lane];
        float s = v.x + v.y + v.z + v.w;
        #pragma unroll
        for (int o = 16; o > 0; o >>= 1) s += __shfl_xor_sync(0xffffffffu, s, o);
        float mu = s * (1.f / 128.f);
        float dx = v.x - mu, dy = v.y - mu, dz = v.z - mu, dw = v.w - mu;
        float ss = dx * dx + dy * dy + dz * dz + dw * dw;
        #pragma unroll
        for (int o = 16; o > 0; o >>= 1) ss += __shfl_xor_sync(0xffffffffu, ss, o);
        float rstd = rsqrtf(ss * (1.f / 128.f) + 1e-5f);
        float4 gg  = ((const float4*)lng)[lane];
        float4 bb2 = ((const float4*)lnb)[lane];
        float4 o4;
        o4.x = dx * rstd * gg.x + bb2.x;
        o4.y = dy * rstd * gg.y + bb2.y;
        o4.z = dz * rstd * gg.z + bb2.z;
        o4.w = dw * rstd * gg.w + bb2.w;
        ((float4*)(out + (size_t)(b * SS + q0 + wid) * DD))[lane] = o4;
    }
}

// ---------------------------------------------------------------------------
extern "C" void kernel_launch(void* const* d_in, const int* in_sizes, int n_in,
                              void* d_out, int out_size)
{
    const float* x    = (const float*)d_in[0];
    const float* st   = (const float*)d_in[1];
    const int*   mask = (const int*)  d_in[2];
    const float* wq   = (const float*)d_in[3];
    const float* bq   = (const float*)d_in[4];
    const float* wk   = (const float*)d_in[5];
    const float* bk   = (const float*)d_in[6];
    const float* wv   = (const float*)d_in[7];
    const float* bv   = (const float*)d_in[8];
    const float* wo   = (const float*)d_in[9];
    const float* bo   = (const float*)d_in[10];
    const float* wst  = (const float*)d_in[11];
    const float* lng  = (const float*)d_in[12];
    const float* lnb  = (const float*)d_in[13];
    float* out = (float*)d_out;

    const int SMEM_QKV  = (128 * 128 + 16 * 128) * 4;                          // 73728 B
    const int SMEM_MEGA = (32 * SCP + 10240 + 512 + 512 + 32 + 1024) * 4;      // 115328 B
    cudaFuncSetAttribute(qkv_kernel,  cudaFuncAttributeMaxDynamicSharedMemorySize, SMEM_QKV);
    cudaFuncSetAttribute(mega_kernel, cudaFuncAttributeMaxDynamicSharedMemorySize, SMEM_MEGA);

    qkv_kernel<<<dim3(128, 3), 256, SMEM_QKV>>>(x, wq, bq, wk, bk, wv, bv);
    mega_kernel<<<512, 256, SMEM_MEGA>>>(st, wst, mask, x, wo, bo, lng, lnb, out);
}